// round 11
// baseline (speedup 1.0000x reference)
#include <cuda_runtime.h>
#include <cuda_bf16.h>
#include <cstdint>

#define B_   16
#define N_   1024
#define DIN_ 256
#define H_   4
#define F_   64
#define OUT_ 256

// -------- scratch (device globals) --------
__device__ float g_esrc[B_ * H_ * N_];
__device__ float g_edst[B_ * H_ * N_];
// Interleaved B-fragment tiles: per (b, hd, chunk): 32 cols x 64 f, uint4 =
// {hi(j0,j0+1), hi(j0+8,j0+9), lo(j0,j0+1), lo(j0+8,j0+9)}, col = kt*4+cc,
// j0 = chunk*128 + kt*16 + 2cc. Layout [col][f] for coalesced stores.
__device__ uint4 g_hTi[B_ * H_ * 8 * 2048];

// bf16 split helpers
__device__ __forceinline__ uint32_t hi_pack(float v0, float v1) {
    uint32_t r;
    asm("prmt.b32 %0, %1, %2, 0x7632;" : "=r"(r)
        : "r"(__float_as_uint(v0)), "r"(__float_as_uint(v1)));
    return r;
}
__device__ __forceinline__ uint32_t lo_pack(float v0, float v1) {
    float l0 = v0 - __uint_as_float(__float_as_uint(v0) & 0xFFFF0000u);
    float l1 = v1 - __uint_as_float(__float_as_uint(v1) & 0xFFFF0000u);
    uint32_t r;
    asm("cvt.rn.bf16x2.f32 %0, %1, %2;" : "=r"(r) : "f"(l1), "f"(l0));
    return r;
}

// warp-level bf16 MMA (HMMA path, sm_80+)
__device__ __forceinline__ void mma16816(float* c, uint32_t a0, uint32_t a1,
                                         uint32_t a2, uint32_t a3,
                                         uint32_t b0, uint32_t b1) {
    asm volatile(
        "mma.sync.aligned.m16n8k16.row.col.f32.bf16.bf16.f32 "
        "{%0,%1,%2,%3}, {%4,%5,%6,%7}, {%8,%9}, {%0,%1,%2,%3};"
        : "+f"(c[0]), "+f"(c[1]), "+f"(c[2]), "+f"(c[3])
        : "r"(a0), "r"(a1), "r"(a2), "r"(a3), "r"(b0), "r"(b1));
}

__device__ __forceinline__ uint32_t smem_u32(const void* p) {
    uint32_t a;
    asm("{ .reg .u64 t; cvta.to.shared.u64 t, %1; cvt.u32.u64 %0, t; }" : "=r"(a) : "l"(p));
    return a;
}
#define CP_ASYNC16(dst, src) \
    asm volatile("cp.async.cg.shared.global [%0], [%1], 16;" :: "r"(dst), "l"(src))
#define CP_COMMIT() asm volatile("cp.async.commit_group;" ::: "memory")
#define CP_WAIT0()  asm volatile("cp.async.wait_group 0;" ::: "memory")

// ============================================================================
// Kernel 1: h = x @ W via split-bf16 HMMA, register-double-buffered stages.
// CTA = 128 rows (one b,chunk) x 128 cols (2 heads); grid (128, 2); 8 warps.
// Epilogue: e_src/e_dst reductions + direct production of attn B-frag tiles
// (g_hTi) from acc registers via smem transpose — no transpose kernel.
// Static smem only (35 KB).
// ============================================================================
__global__ __launch_bounds__(256, 2) void gemm_h_mma_kernel(
    const float* __restrict__ x, const float* __restrict__ W,
    const float* __restrict__ a_src, const float* __restrict__ a_dst)
{
    __shared__ __align__(16) char smem_raw[35840];
    float*    sAs = (float*)smem_raw;                       // [0,1024)
    float*    sAd = (float*)(smem_raw + 1024);              // [1024,2048)
    uint32_t* sxh = (uint32_t*)(smem_raw + 2048);           // 6144 B
    uint32_t* sxl = (uint32_t*)(smem_raw + 2048 + 6144);    // 6144 B
    uint4*    swt = (uint4*)(smem_raw + 2048 + 12288);      // 8192 B
    float*    sht = (float*)(smem_raw + 2048);              // 33792 B (reuse)

    const int tid = threadIdx.x;
    const int wid = tid >> 5;
    const int l   = tid & 31;
    const int q   = l >> 2;
    const int c   = l & 3;
    const int R0  = blockIdx.x * 128;
    const int F0  = blockIdx.y * 128;

    sAs[tid] = a_src[tid];
    sAd[tid] = a_dst[tid];

    float acc[16][4];
#pragma unroll
    for (int nt = 0; nt < 16; nt++)
#pragma unroll
        for (int k = 0; k < 4; k++) acc[nt][k] = 0.f;

    const int xr = tid >> 1, xh = tid & 1;
    const int wf = tid >> 1, wh = tid & 1;

    // register prefetch buffers
    float4 pxa, pxb;
    float  pw[2][4];

    {   // prologue: load kt = 0
        const float* xp = x + (size_t)(R0 + xr) * DIN_ + xh * 8;
        pxa = *(const float4*)xp;
        pxb = *(const float4*)(xp + 4);
#pragma unroll
        for (int t = 0; t < 2; t++) {
            int cc = wh * 2 + t;
            const float* wp = W + (size_t)(2 * cc) * OUT_ + F0 + wf;
            pw[t][0] = wp[0]; pw[t][1] = wp[OUT_];
            pw[t][2] = wp[8 * OUT_]; pw[t][3] = wp[9 * OUT_];
        }
    }

    for (int kt = 0; kt < 16; kt++) {
        __syncthreads();   // stage buffers free
        {
            uint4 hi = make_uint4(hi_pack(pxa.x, pxa.y), hi_pack(pxa.z, pxa.w),
                                  hi_pack(pxb.x, pxb.y), hi_pack(pxb.z, pxb.w));
            uint4 lo = make_uint4(lo_pack(pxa.x, pxa.y), lo_pack(pxa.z, pxa.w),
                                  lo_pack(pxb.x, pxb.y), lo_pack(pxb.z, pxb.w));
            *(uint4*)&sxh[xr * 12 + xh * 4] = hi;
            *(uint4*)&sxl[xr * 12 + xh * 4] = lo;
#pragma unroll
            for (int t = 0; t < 2; t++) {
                int cc = wh * 2 + t;
                swt[wf * 4 + cc] =
                    make_uint4(hi_pack(pw[t][0], pw[t][1]), hi_pack(pw[t][2], pw[t][3]),
                               lo_pack(pw[t][0], pw[t][1]), lo_pack(pw[t][2], pw[t][3]));
            }
        }
        __syncthreads();
        // prefetch kt+1 (overlaps mma below)
        if (kt < 15) {
            const float* xp = x + (size_t)(R0 + xr) * DIN_ + (kt + 1) * 16 + xh * 8;
            pxa = *(const float4*)xp;
            pxb = *(const float4*)(xp + 4);
#pragma unroll
            for (int t = 0; t < 2; t++) {
                int cc = wh * 2 + t;
                const float* wp = W + (size_t)((kt + 1) * 16 + 2 * cc) * OUT_ + F0 + wf;
                pw[t][0] = wp[0]; pw[t][1] = wp[OUT_];
                pw[t][2] = wp[8 * OUT_]; pw[t][3] = wp[9 * OUT_];
            }
        }

        const int r0 = wid * 16 + q;
        const uint32_t ah0 = sxh[r0 * 12 + c];
        const uint32_t ah1 = sxh[(r0 + 8) * 12 + c];
        const uint32_t ah2 = sxh[r0 * 12 + c + 4];
        const uint32_t ah3 = sxh[(r0 + 8) * 12 + c + 4];
        const uint32_t al0 = sxl[r0 * 12 + c];
        const uint32_t al1 = sxl[(r0 + 8) * 12 + c];
        const uint32_t al2 = sxl[r0 * 12 + c + 4];
        const uint32_t al3 = sxl[(r0 + 8) * 12 + c + 4];

#pragma unroll
        for (int nt = 0; nt < 16; nt++) {
            uint4 v = swt[(nt * 8 + q) * 4 + c];
            mma16816(acc[nt], ah0, ah1, ah2, ah3, v.x, v.y);
            mma16816(acc[nt], ah0, ah1, ah2, ah3, v.z, v.w);
            mma16816(acc[nt], al0, al1, al2, al3, v.x, v.y);
        }
    }

    // ---- epilogue A: e_src/e_dst reductions ----
    const int gr0   = R0 + wid * 16 + q;
    const int b     = gr0 >> 10;
    const int n     = gr0 & (N_ - 1);
    const int chunk = (R0 >> 7) & 7;
#pragma unroll
    for (int hh = 0; hh < 2; hh++) {
        float ps0 = 0.f, ps1 = 0.f, pd0 = 0.f, pd1 = 0.f;
#pragma unroll
        for (int t = 0; t < 8; t++) {
            const int nt = hh * 8 + t;
            const int gc = F0 + nt * 8 + 2 * c;
            float2 as2 = *(float2*)&sAs[gc];
            float2 ad2 = *(float2*)&sAd[gc];
            ps0 += acc[nt][0] * as2.x + acc[nt][1] * as2.y;
            ps1 += acc[nt][2] * as2.x + acc[nt][3] * as2.y;
            pd0 += acc[nt][0] * ad2.x + acc[nt][1] * ad2.y;
            pd1 += acc[nt][2] * ad2.x + acc[nt][3] * ad2.y;
        }
#pragma unroll
        for (int off = 1; off <= 2; off <<= 1) {
            ps0 += __shfl_xor_sync(0xffffffffu, ps0, off);
            ps1 += __shfl_xor_sync(0xffffffffu, ps1, off);
            pd0 += __shfl_xor_sync(0xffffffffu, pd0, off);
            pd1 += __shfl_xor_sync(0xffffffffu, pd1, off);
        }
        if (c == 0) {
            const int hd = blockIdx.y * 2 + hh;
            g_esrc[(b * H_ + hd) * N_ + n]     = ps0;
            g_esrc[(b * H_ + hd) * N_ + n + 8] = ps1;
            g_edst[(b * H_ + hd) * N_ + n]     = pd0;
            g_edst[(b * H_ + hd) * N_ + n + 8] = pd1;
        }
    }

    // ---- epilogue B: produce g_hTi B-frag tiles (per head) ----
#pragma unroll 1
    for (int hh = 0; hh < 2; hh++) {
        __syncthreads();   // sht region free
        {
            const int j0 = wid * 16 + q;
#pragma unroll
            for (int t = 0; t < 8; t++) {
                const int nt = hh * 8 + t;
                const int f0 = t * 8 + 2 * c;
                *(float2*)&sht[j0 * 66 + f0]       = make_float2(acc[nt][0], acc[nt][1]);
                *(float2*)&sht[(j0 + 8) * 66 + f0] = make_float2(acc[nt][2], acc[nt][3]);
            }
        }
        __syncthreads();
        {
            const int hd = blockIdx.y * 2 + hh;
            uint4* gt = g_hTi + ((size_t)((b * H_ + hd) * 8 + chunk)) * 2048;
            const int f = tid & 63;
            const int g = tid >> 6;      // 0..3
#pragma unroll
            for (int v = 0; v < 8; v++) {
                const int col = g * 8 + v;
                const int kt  = col >> 2;
                const int cc  = col & 3;
                const int j0  = kt * 16 + 2 * cc;
                float a0 = sht[j0 * 66 + f];
                float a1 = sht[(j0 + 1) * 66 + f];
                float a2 = sht[(j0 + 8) * 66 + f];
                float a3 = sht[(j0 + 9) * 66 + f];
                gt[col * 64 + f] = make_uint4(hi_pack(a0, a1), hi_pack(a2, a3),
                                              lo_pack(a0, a1), lo_pack(a2, a3));
            }
        }
    }
}

// ============================================================================
// Kernel 2: HMMA flash-GAT, head-split, cp.async double-buffered HALF-chunk
// B tiles (64 f x 16 cols), all smem STATIC (45 KB, no opt-in, no attribute).
// 32 steps: s -> (chunk = s>>2, hh = (s>>1)&1, half = s&1). Tile s+1
// prefetched via cp.async during step s.
// Buffer stride 20 uint4 (== 4 mod 8 -> conflict-free LDS.128 reads).
// ============================================================================
#define CSTR 20

__global__ __launch_bounds__(256, 2) void gat_attn_mma_kernel(
    const float* __restrict__ adj, const float* __restrict__ bias,
    float* __restrict__ out)
{
    __shared__ uint32_t abits[128][4];
    __shared__ float    es_sh[2][128];
    __shared__ float    ed_sh[2][128];
    __shared__ __align__(16) uint4 hbuf[2][64 * CSTR];   // 2 x 20480 B

    const int tid = threadIdx.x;
    const int wid = tid >> 5;
    const int l   = tid & 31;
    const int q   = l >> 2;
    const int c   = l & 3;
    const int b   = blockIdx.y;
    const int i0  = blockIdx.x * 128;
    const int hp  = blockIdx.z;

    for (int idx = tid; idx < 2 * 128; idx += 256)
        ed_sh[idx >> 7][idx & 127] =
            g_edst[(b * H_ + hp * 2 + (idx >> 7)) * N_ + i0 + (idx & 127)];

    float acc[2][8][4];
    float den[2][2];
#pragma unroll
    for (int hh = 0; hh < 2; hh++) {
        den[hh][0] = 0.f; den[hh][1] = 0.f;
#pragma unroll
        for (int nt = 0; nt < 8; nt++)
#pragma unroll
            for (int k = 0; k < 4; k++) acc[hh][nt][k] = 0.f;
    }

    const float* adj_b = adj + (size_t)b * N_ * N_;
    const uint4* gt = g_hTi + ((size_t)(b * H_ + hp * 2) * 8) * 2048;

    // prefetch tile for step s: chunk = s>>2, hh = (s>>1)&1, half = s&1
    auto issue_stage = [&](int s) {
        const uint4* src = gt + (size_t)(((s >> 1) & 1) * 8 + (s >> 2)) * 2048
                              + (s & 1) * 1024;
        uint4* dstb = hbuf[s & 1];
#pragma unroll
        for (int v = 0; v < 4; v++) {
            int idx = tid + v * 256;             // 0..1023
            int f = idx & 63, col = idx >> 6;    // col 0..15
            CP_ASYNC16(smem_u32(dstb + f * CSTR + col), src + idx);
        }
        CP_COMMIT();
    };

    issue_stage(0);

    for (int s = 0; s < 32; s++) {
        const int hh   = (s >> 1) & 1;
        const int half = s & 1;
        const int j0c  = (s >> 2) * 128;        // chunk base j

        CP_WAIT0();
        __syncthreads();                        // tile s visible; step s-1 done
        if (s + 1 < 32) issue_stage(s + 1);     // flies during this step

        if ((s & 3) == 0) {
            // new chunk: adjacency bitmask + e_src for both heads
#pragma unroll 4
            for (int k = 0; k < 16; k++) {
                int r = wid * 16 + k;
                const float* arow = adj_b + (size_t)(i0 + r) * N_ + j0c;
#pragma unroll
                for (int jg = 0; jg < 4; jg++) {
                    uint32_t m = __ballot_sync(0xffffffffu, arow[jg * 32 + l] > 0.5f);
                    if (l == 0) abits[r][jg] = m;
                }
            }
            for (int idx = tid; idx < 2 * 128; idx += 256)
                es_sh[idx >> 7][idx & 127] =
                    g_esrc[(b * H_ + hp * 2 + (idx >> 7)) * N_ + j0c + (idx & 127)];
            __syncthreads();
        }

        const uint4* hbi = hbuf[s & 1];
        const int r0 = wid * 16 + q;
        const float ed0 = ed_sh[hh][r0];
        const float ed1 = ed_sh[hh][r0 + 8];
        float dsum0 = 0.f, dsum1 = 0.f;
#pragma unroll
        for (int ktl = 0; ktl < 4; ktl++) {
            const int gkt = half * 4 + ktl;
            const int jA = gkt * 16 + c * 2;
            float2 eA = *(const float2*)&es_sh[hh][jA];
            float2 eB = *(const float2*)&es_sh[hh][jA + 8];
            const uint32_t w0 = abits[r0][gkt >> 1];
            const uint32_t w1 = abits[r0 + 8][gkt >> 1];
            const int bb = ((gkt & 1) << 4) + c * 2;

            float p00, p01, p08, p09, p10, p11, p18, p19;
            {
                float s_;
                s_ = ed0 + eA.x; s_ = fmaxf(s_, 0.2f * s_); p00 = ((w0 >> bb) & 1u) ? __expf(s_) : 0.f;
                s_ = ed0 + eA.y; s_ = fmaxf(s_, 0.2f * s_); p01 = ((w0 >> (bb + 1)) & 1u) ? __expf(s_) : 0.f;
                s_ = ed0 + eB.x; s_ = fmaxf(s_, 0.2f * s_); p08 = ((w0 >> (bb + 8)) & 1u) ? __expf(s_) : 0.f;
                s_ = ed0 + eB.y; s_ = fmaxf(s_, 0.2f * s_); p09 = ((w0 >> (bb + 9)) & 1u) ? __expf(s_) : 0.f;
                s_ = ed1 + eA.x; s_ = fmaxf(s_, 0.2f * s_); p10 = ((w1 >> bb) & 1u) ? __expf(s_) : 0.f;
                s_ = ed1 + eA.y; s_ = fmaxf(s_, 0.2f * s_); p11 = ((w1 >> (bb + 1)) & 1u) ? __expf(s_) : 0.f;
                s_ = ed1 + eB.x; s_ = fmaxf(s_, 0.2f * s_); p18 = ((w1 >> (bb + 8)) & 1u) ? __expf(s_) : 0.f;
                s_ = ed1 + eB.y; s_ = fmaxf(s_, 0.2f * s_); p19 = ((w1 >> (bb + 9)) & 1u) ? __expf(s_) : 0.f;
            }
            dsum0 += (p00 + p01) + (p08 + p09);
            dsum1 += (p10 + p11) + (p18 + p19);

            const uint32_t a0h = hi_pack(p00, p01), a1h = hi_pack(p10, p11);
            const uint32_t a2h = hi_pack(p08, p09), a3h = hi_pack(p18, p19);
            const uint32_t a0l = lo_pack(p00, p01), a1l = lo_pack(p10, p11);
            const uint32_t a2l = lo_pack(p08, p09), a3l = lo_pack(p18, p19);

#pragma unroll
            for (int nt = 0; nt < 8; nt++) {
                uint4 v = hbi[(nt * 8 + q) * CSTR + ktl * 4 + c];
                mma16816(acc[hh][nt], a0h, a1h, a2h, a3h, v.x, v.y);
                mma16816(acc[hh][nt], a0h, a1h, a2h, a3h, v.z, v.w);
                mma16816(acc[hh][nt], a0l, a1l, a2l, a3l, v.x, v.y);
            }
        }
        den[hh][0] += dsum0;
        den[hh][1] += dsum1;
    }

    // ---- epilogue: out = acc / den + bias ----
    const int gr0 = b * N_ + i0 + wid * 16 + q;
#pragma unroll
    for (int hh = 0; hh < 2; hh++) {
        float d0 = den[hh][0];
        d0 += __shfl_xor_sync(0xffffffffu, d0, 1);
        d0 += __shfl_xor_sync(0xffffffffu, d0, 2);
        float d1 = den[hh][1];
        d1 += __shfl_xor_sync(0xffffffffu, d1, 1);
        d1 += __shfl_xor_sync(0xffffffffu, d1, 2);
        const float rl0 = 1.0f / d0, rl1 = 1.0f / d1;
#pragma unroll
        for (int nt = 0; nt < 8; nt++) {
            const int col = (hp * 2 + hh) * 64 + nt * 8 + c * 2;
            float2 bv = __ldg((const float2*)(bias + col));
            float2 o0, o1;
            o0.x = acc[hh][nt][0] * rl0 + bv.x;
            o0.y = acc[hh][nt][1] * rl0 + bv.y;
            o1.x = acc[hh][nt][2] * rl1 + bv.x;
            o1.y = acc[hh][nt][3] * rl1 + bv.y;
            *(float2*)(out + (size_t)gr0 * OUT_ + col)       = o0;
            *(float2*)(out + (size_t)(gr0 + 8) * OUT_ + col) = o1;
        }
    }
}

// ============================================================================
extern "C" void kernel_launch(void* const* d_in, const int* in_sizes, int n_in,
                              void* d_out, int out_size)
{
    const float* x     = (const float*)d_in[0];
    const float* adj   = (const float*)d_in[1];
    const float* W     = (const float*)d_in[2];
    const float* a_src = (const float*)d_in[3];
    const float* a_dst = (const float*)d_in[4];
    const float* bias  = (const float*)d_in[5];
    float* out = (float*)d_out;

    gemm_h_mma_kernel<<<dim3((B_ * N_) / 128, 2), 256>>>(x, W, a_src, a_dst);
    gat_attn_mma_kernel<<<dim3(N_ / 128, B_, 2), 256>>>(adj, bias, out);
}

// round 12
// speedup vs baseline: 1.0757x; 1.0757x over previous
#include <cuda_runtime.h>
#include <cuda_bf16.h>
#include <cstdint>

#define B_   16
#define N_   1024
#define DIN_ 256
#define H_   4
#define F_   64
#define OUT_ 256

// -------- scratch (device globals) --------
__device__ float g_esrc[B_ * H_ * N_];
__device__ float g_edst[B_ * H_ * N_];
// Interleaved B-fragment tiles, f-major: per (b, hd, chunk): gt[f*32 + col],
// f = feature 0..63, col = kt*4+cc (j0 = chunk*128 + kt*16 + 2cc), uint4 =
// {hi(j0,j0+1), hi(j0+8,j0+9), lo(j0,j0+1), lo(j0+8,j0+9)}.
__device__ uint4 g_hTi[B_ * H_ * 8 * 2048];

// bf16 split helpers
__device__ __forceinline__ uint32_t hi_pack(float v0, float v1) {
    uint32_t r;
    asm("prmt.b32 %0, %1, %2, 0x7632;" : "=r"(r)
        : "r"(__float_as_uint(v0)), "r"(__float_as_uint(v1)));
    return r;
}
__device__ __forceinline__ uint32_t lo_pack(float v0, float v1) {
    float l0 = v0 - __uint_as_float(__float_as_uint(v0) & 0xFFFF0000u);
    float l1 = v1 - __uint_as_float(__float_as_uint(v1) & 0xFFFF0000u);
    uint32_t r;
    asm("cvt.rn.bf16x2.f32 %0, %1, %2;" : "=r"(r) : "f"(l1), "f"(l0));
    return r;
}

// warp-level bf16 MMA (HMMA path, sm_80+)
__device__ __forceinline__ void mma16816(float* c, uint32_t a0, uint32_t a1,
                                         uint32_t a2, uint32_t a3,
                                         uint32_t b0, uint32_t b1) {
    asm volatile(
        "mma.sync.aligned.m16n8k16.row.col.f32.bf16.bf16.f32 "
        "{%0,%1,%2,%3}, {%4,%5,%6,%7}, {%8,%9}, {%0,%1,%2,%3};"
        : "+f"(c[0]), "+f"(c[1]), "+f"(c[2]), "+f"(c[3])
        : "r"(a0), "r"(a1), "r"(a2), "r"(a3), "r"(b0), "r"(b1));
}

__device__ __forceinline__ uint32_t smem_u32(const void* p) {
    uint32_t a;
    asm("{ .reg .u64 t; cvta.to.shared.u64 t, %1; cvt.u32.u64 %0, t; }" : "=r"(a) : "l"(p));
    return a;
}
#define CP_ASYNC16(dst, src) \
    asm volatile("cp.async.cg.shared.global [%0], [%1], 16;" :: "r"(dst), "l"(src))
#define CP_COMMIT() asm volatile("cp.async.commit_group;" ::: "memory")
#define CP_WAIT0()  asm volatile("cp.async.wait_group 0;" ::: "memory")

// ============================================================================
// Kernel 1: h = x @ W via split-bf16 HMMA, register-double-buffered stages.
// CTA = 128 rows (one b,chunk) x 128 cols (2 heads); grid (128, 2); 8 warps.
// Epilogue: e_src/e_dst reductions + direct production of attn B-frag tiles
// (g_hTi, f-major) from acc registers via smem transpose.
// Static smem only (35 KB).
// ============================================================================
__global__ __launch_bounds__(256, 2) void gemm_h_mma_kernel(
    const float* __restrict__ x, const float* __restrict__ W,
    const float* __restrict__ a_src, const float* __restrict__ a_dst)
{
    __shared__ __align__(16) char smem_raw[35840];
    float*    sAs = (float*)smem_raw;                       // [0,1024)
    float*    sAd = (float*)(smem_raw + 1024);              // [1024,2048)
    uint32_t* sxh = (uint32_t*)(smem_raw + 2048);           // 6144 B
    uint32_t* sxl = (uint32_t*)(smem_raw + 2048 + 6144);    // 6144 B
    uint4*    swt = (uint4*)(smem_raw + 2048 + 12288);      // 8192 B
    float*    sht = (float*)(smem_raw + 2048);              // 33792 B (reuse)

    const int tid = threadIdx.x;
    const int wid = tid >> 5;
    const int l   = tid & 31;
    const int q   = l >> 2;
    const int c   = l & 3;
    const int R0  = blockIdx.x * 128;
    const int F0  = blockIdx.y * 128;

    sAs[tid] = a_src[tid];
    sAd[tid] = a_dst[tid];

    float acc[16][4];
#pragma unroll
    for (int nt = 0; nt < 16; nt++)
#pragma unroll
        for (int k = 0; k < 4; k++) acc[nt][k] = 0.f;

    const int xr = tid >> 1, xh = tid & 1;
    const int wf = tid >> 1, wh = tid & 1;

    float4 pxa, pxb;
    float  pw[2][4];

    {   // prologue: load kt = 0
        const float* xp = x + (size_t)(R0 + xr) * DIN_ + xh * 8;
        pxa = *(const float4*)xp;
        pxb = *(const float4*)(xp + 4);
#pragma unroll
        for (int t = 0; t < 2; t++) {
            int cc = wh * 2 + t;
            const float* wp = W + (size_t)(2 * cc) * OUT_ + F0 + wf;
            pw[t][0] = wp[0]; pw[t][1] = wp[OUT_];
            pw[t][2] = wp[8 * OUT_]; pw[t][3] = wp[9 * OUT_];
        }
    }

    for (int kt = 0; kt < 16; kt++) {
        __syncthreads();
        {
            uint4 hi = make_uint4(hi_pack(pxa.x, pxa.y), hi_pack(pxa.z, pxa.w),
                                  hi_pack(pxb.x, pxb.y), hi_pack(pxb.z, pxb.w));
            uint4 lo = make_uint4(lo_pack(pxa.x, pxa.y), lo_pack(pxa.z, pxa.w),
                                  lo_pack(pxb.x, pxb.y), lo_pack(pxb.z, pxb.w));
            *(uint4*)&sxh[xr * 12 + xh * 4] = hi;
            *(uint4*)&sxl[xr * 12 + xh * 4] = lo;
#pragma unroll
            for (int t = 0; t < 2; t++) {
                int cc = wh * 2 + t;
                swt[wf * 4 + cc] =
                    make_uint4(hi_pack(pw[t][0], pw[t][1]), hi_pack(pw[t][2], pw[t][3]),
                               lo_pack(pw[t][0], pw[t][1]), lo_pack(pw[t][2], pw[t][3]));
            }
        }
        __syncthreads();
        if (kt < 15) {
            const float* xp = x + (size_t)(R0 + xr) * DIN_ + (kt + 1) * 16 + xh * 8;
            pxa = *(const float4*)xp;
            pxb = *(const float4*)(xp + 4);
#pragma unroll
            for (int t = 0; t < 2; t++) {
                int cc = wh * 2 + t;
                const float* wp = W + (size_t)((kt + 1) * 16 + 2 * cc) * OUT_ + F0 + wf;
                pw[t][0] = wp[0]; pw[t][1] = wp[OUT_];
                pw[t][2] = wp[8 * OUT_]; pw[t][3] = wp[9 * OUT_];
            }
        }

        const int r0 = wid * 16 + q;
        const uint32_t ah0 = sxh[r0 * 12 + c];
        const uint32_t ah1 = sxh[(r0 + 8) * 12 + c];
        const uint32_t ah2 = sxh[r0 * 12 + c + 4];
        const uint32_t ah3 = sxh[(r0 + 8) * 12 + c + 4];
        const uint32_t al0 = sxl[r0 * 12 + c];
        const uint32_t al1 = sxl[(r0 + 8) * 12 + c];
        const uint32_t al2 = sxl[r0 * 12 + c + 4];
        const uint32_t al3 = sxl[(r0 + 8) * 12 + c + 4];

#pragma unroll
        for (int nt = 0; nt < 16; nt++) {
            uint4 v = swt[(nt * 8 + q) * 4 + c];
            mma16816(acc[nt], ah0, ah1, ah2, ah3, v.x, v.y);
            mma16816(acc[nt], ah0, ah1, ah2, ah3, v.z, v.w);
            mma16816(acc[nt], al0, al1, al2, al3, v.x, v.y);
        }
    }

    // ---- epilogue A: e_src/e_dst reductions ----
    const int gr0   = R0 + wid * 16 + q;
    const int b     = gr0 >> 10;
    const int n     = gr0 & (N_ - 1);
    const int chunk = (R0 >> 7) & 7;
#pragma unroll
    for (int hh = 0; hh < 2; hh++) {
        float ps0 = 0.f, ps1 = 0.f, pd0 = 0.f, pd1 = 0.f;
#pragma unroll
        for (int t = 0; t < 8; t++) {
            const int nt = hh * 8 + t;
            const int gc = F0 + nt * 8 + 2 * c;
            float2 as2 = *(float2*)&sAs[gc];
            float2 ad2 = *(float2*)&sAd[gc];
            ps0 += acc[nt][0] * as2.x + acc[nt][1] * as2.y;
            ps1 += acc[nt][2] * as2.x + acc[nt][3] * as2.y;
            pd0 += acc[nt][0] * ad2.x + acc[nt][1] * ad2.y;
            pd1 += acc[nt][2] * ad2.x + acc[nt][3] * ad2.y;
        }
#pragma unroll
        for (int off = 1; off <= 2; off <<= 1) {
            ps0 += __shfl_xor_sync(0xffffffffu, ps0, off);
            ps1 += __shfl_xor_sync(0xffffffffu, ps1, off);
            pd0 += __shfl_xor_sync(0xffffffffu, pd0, off);
            pd1 += __shfl_xor_sync(0xffffffffu, pd1, off);
        }
        if (c == 0) {
            const int hd = blockIdx.y * 2 + hh;
            g_esrc[(b * H_ + hd) * N_ + n]     = ps0;
            g_esrc[(b * H_ + hd) * N_ + n + 8] = ps1;
            g_edst[(b * H_ + hd) * N_ + n]     = pd0;
            g_edst[(b * H_ + hd) * N_ + n + 8] = pd1;
        }
    }

    // ---- epilogue B: produce g_hTi B-frag tiles (f-major, per head) ----
#pragma unroll 1
    for (int hh = 0; hh < 2; hh++) {
        __syncthreads();   // sht region free
        {
            const int j0 = wid * 16 + q;
#pragma unroll
            for (int t = 0; t < 8; t++) {
                const int nt = hh * 8 + t;
                const int f0 = t * 8 + 2 * c;
                *(float2*)&sht[j0 * 66 + f0]       = make_float2(acc[nt][0], acc[nt][1]);
                *(float2*)&sht[(j0 + 8) * 66 + f0] = make_float2(acc[nt][2], acc[nt][3]);
            }
        }
        __syncthreads();
        {
            const int hd = blockIdx.y * 2 + hh;
            uint4* gt = g_hTi + ((size_t)((b * H_ + hd) * 8 + chunk)) * 2048;
            const int col = tid & 31;          // kt*4 + cc
            const int fb  = tid >> 5;          // 0..7
            const int kt  = col >> 2;
            const int cc  = col & 3;
            const int j0  = kt * 16 + 2 * cc;
#pragma unroll
            for (int v = 0; v < 8; v++) {
                const int f = fb * 8 + v;
                float a0 = sht[j0 * 66 + f];
                float a1 = sht[(j0 + 1) * 66 + f];
                float a2 = sht[(j0 + 8) * 66 + f];
                float a3 = sht[(j0 + 9) * 66 + f];
                gt[f * 32 + col] = make_uint4(hi_pack(a0, a1), hi_pack(a2, a3),
                                              lo_pack(a0, a1), lo_pack(a2, a3));
            }
        }
    }
}

// ============================================================================
// Kernel 2: HMMA flash-GAT, head-split, cp.async double-buffered HALF-chunk
// B tiles (64 f x 16 cols), static smem (45 KB). 32 steps:
// s -> (chunk = s>>2, hh = (s>>1)&1, half = s&1); tile s+1 prefetched during
// step s. Stage: lanes map col-fastest -> coalesced src, conflict-free dst.
// Buffer row stride 20 uint4 (== 4 mod 8 -> conflict-free LDS.128 reads).
// ============================================================================
#define CSTR 20

__global__ __launch_bounds__(256, 2) void gat_attn_mma_kernel(
    const float* __restrict__ adj, const float* __restrict__ bias,
    float* __restrict__ out)
{
    __shared__ uint32_t abits[128][4];
    __shared__ float    es_sh[2][128];
    __shared__ float    ed_sh[2][128];
    __shared__ __align__(16) uint4 hbuf[2][64 * CSTR];   // 2 x 20480 B

    const int tid = threadIdx.x;
    const int wid = tid >> 5;
    const int l   = tid & 31;
    const int q   = l >> 2;
    const int c   = l & 3;
    const int b   = blockIdx.y;
    const int i0  = blockIdx.x * 128;
    const int hp  = blockIdx.z;

    for (int idx = tid; idx < 2 * 128; idx += 256)
        ed_sh[idx >> 7][idx & 127] =
            g_edst[(b * H_ + hp * 2 + (idx >> 7)) * N_ + i0 + (idx & 127)];

    float acc[2][8][4];
    float den[2][2];
#pragma unroll
    for (int hh = 0; hh < 2; hh++) {
        den[hh][0] = 0.f; den[hh][1] = 0.f;
#pragma unroll
        for (int nt = 0; nt < 8; nt++)
#pragma unroll
            for (int k = 0; k < 4; k++) acc[hh][nt][k] = 0.f;
    }

    const float* adj_b = adj + (size_t)b * N_ * N_;
    const uint4* gt = g_hTi + ((size_t)(b * H_ + hp * 2) * 8) * 2048;

    // prefetch tile for step s: chunk = s>>2, hh = (s>>1)&1, half = s&1
    auto issue_stage = [&](int s) {
        const uint4* src = gt + (size_t)(((s >> 1) & 1) * 8 + (s >> 2)) * 2048
                              + (s & 1) * 16;
        uint4* dstb = hbuf[s & 1];
#pragma unroll
        for (int v = 0; v < 4; v++) {
            int idx = tid + v * 256;             // 0..1023
            int f = idx >> 4, colL = idx & 15;   // col fastest
            CP_ASYNC16(smem_u32(dstb + f * CSTR + colL), src + f * 32 + colL);
        }
        CP_COMMIT();
    };

    issue_stage(0);

    for (int s = 0; s < 32; s++) {
        const int hh   = (s >> 1) & 1;
        const int half = s & 1;
        const int j0c  = (s >> 2) * 128;        // chunk base j

        CP_WAIT0();
        __syncthreads();                        // tile s visible; step s-1 done
        if (s + 1 < 32) issue_stage(s + 1);     // flies during this step

        if ((s & 3) == 0) {
            // new chunk: adjacency bitmask + e_src for both heads
#pragma unroll 4
            for (int k = 0; k < 16; k++) {
                int r = wid * 16 + k;
                const float* arow = adj_b + (size_t)(i0 + r) * N_ + j0c;
#pragma unroll
                for (int jg = 0; jg < 4; jg++) {
                    uint32_t m = __ballot_sync(0xffffffffu, arow[jg * 32 + l] > 0.5f);
                    if (l == 0) abits[r][jg] = m;
                }
            }
            for (int idx = tid; idx < 2 * 128; idx += 256)
                es_sh[idx >> 7][idx & 127] =
                    g_esrc[(b * H_ + hp * 2 + (idx >> 7)) * N_ + j0c + (idx & 127)];
            __syncthreads();
        }

        const uint4* hbi = hbuf[s & 1];
        const int r0 = wid * 16 + q;
        const float ed0 = ed_sh[hh][r0];
        const float ed1 = ed_sh[hh][r0 + 8];
        float dsum0 = 0.f, dsum1 = 0.f;
#pragma unroll
        for (int ktl = 0; ktl < 4; ktl++) {
            const int gkt = half * 4 + ktl;
            const int jA = gkt * 16 + c * 2;
            float2 eA = *(const float2*)&es_sh[hh][jA];
            float2 eB = *(const float2*)&es_sh[hh][jA + 8];
            const uint32_t w0 = abits[r0][gkt >> 1];
            const uint32_t w1 = abits[r0 + 8][gkt >> 1];
            const int bb = ((gkt & 1) << 4) + c * 2;

            float p00, p01, p08, p09, p10, p11, p18, p19;
            {
                float s_;
                s_ = ed0 + eA.x; s_ = fmaxf(s_, 0.2f * s_); p00 = ((w0 >> bb) & 1u) ? __expf(s_) : 0.f;
                s_ = ed0 + eA.y; s_ = fmaxf(s_, 0.2f * s_); p01 = ((w0 >> (bb + 1)) & 1u) ? __expf(s_) : 0.f;
                s_ = ed0 + eB.x; s_ = fmaxf(s_, 0.2f * s_); p08 = ((w0 >> (bb + 8)) & 1u) ? __expf(s_) : 0.f;
                s_ = ed0 + eB.y; s_ = fmaxf(s_, 0.2f * s_); p09 = ((w0 >> (bb + 9)) & 1u) ? __expf(s_) : 0.f;
                s_ = ed1 + eA.x; s_ = fmaxf(s_, 0.2f * s_); p10 = ((w1 >> bb) & 1u) ? __expf(s_) : 0.f;
                s_ = ed1 + eA.y; s_ = fmaxf(s_, 0.2f * s_); p11 = ((w1 >> (bb + 1)) & 1u) ? __expf(s_) : 0.f;
                s_ = ed1 + eB.x; s_ = fmaxf(s_, 0.2f * s_); p18 = ((w1 >> (bb + 8)) & 1u) ? __expf(s_) : 0.f;
                s_ = ed1 + eB.y; s_ = fmaxf(s_, 0.2f * s_); p19 = ((w1 >> (bb + 9)) & 1u) ? __expf(s_) : 0.f;
            }
            dsum0 += (p00 + p01) + (p08 + p09);
            dsum1 += (p10 + p11) + (p18 + p19);

            const uint32_t a0h = hi_pack(p00, p01), a1h = hi_pack(p10, p11);
            const uint32_t a2h = hi_pack(p08, p09), a3h = hi_pack(p18, p19);
            const uint32_t a0l = lo_pack(p00, p01), a1l = lo_pack(p10, p11);
            const uint32_t a2l = lo_pack(p08, p09), a3l = lo_pack(p18, p19);

#pragma unroll
            for (int nt = 0; nt < 8; nt++) {
                uint4 v = hbi[(nt * 8 + q) * CSTR + ktl * 4 + c];
                mma16816(acc[hh][nt], a0h, a1h, a2h, a3h, v.x, v.y);
                mma16816(acc[hh][nt], a0h, a1h, a2h, a3h, v.z, v.w);
                mma16816(acc[hh][nt], a0l, a1l, a2l, a3l, v.x, v.y);
            }
        }
        den[hh][0] += dsum0;
        den[hh][1] += dsum1;
    }

    // ---- epilogue: out = acc / den + bias ----
    const int gr0 = b * N_ + i0 + wid * 16 + q;
#pragma unroll
    for (int hh = 0; hh < 2; hh++) {
        float d0 = den[hh][0];
        d0 += __shfl_xor_sync(0xffffffffu, d0, 1);
        d0 += __shfl_xor_sync(0xffffffffu, d0, 2);
        float d1 = den[hh][1];
        d1 += __shfl_xor_sync(0xffffffffu, d1, 1);
        d1 += __shfl_xor_sync(0xffffffffu, d1, 2);
        const float rl0 = 1.0f / d0, rl1 = 1.0f / d1;
#pragma unroll
        for (int nt = 0; nt < 8; nt++) {
            const int col = (hp * 2 + hh) * 64 + nt * 8 + c * 2;
            float2 bv = __ldg((const float2*)(bias + col));
            float2 o0, o1;
            o0.x = acc[hh][nt][0] * rl0 + bv.x;
            o0.y = acc[hh][nt][1] * rl0 + bv.y;
            o1.x = acc[hh][nt][2] * rl1 + bv.x;
            o1.y = acc[hh][nt][3] * rl1 + bv.y;
            *(float2*)(out + (size_t)gr0 * OUT_ + col)       = o0;
            *(float2*)(out + (size_t)(gr0 + 8) * OUT_ + col) = o1;
        }
    }
}

// ============================================================================
extern "C" void kernel_launch(void* const* d_in, const int* in_sizes, int n_in,
                              void* d_out, int out_size)
{
    const float* x     = (const float*)d_in[0];
    const float* adj   = (const float*)d_in[1];
    const float* W     = (const float*)d_in[2];
    const float* a_src = (const float*)d_in[3];
    const float* a_dst = (const float*)d_in[4];
    const float* bias  = (const float*)d_in[5];
    float* out = (float*)d_out;

    gemm_h_mma_kernel<<<dim3((B_ * N_) / 128, 2), 256>>>(x, W, a_src, a_dst);
    gat_attn_mma_kernel<<<dim3(N_ / 128, B_, 2), 256>>>(adj, bias, out);
}

// round 13
// speedup vs baseline: 1.5261x; 1.4188x over previous
#include <cuda_runtime.h>
#include <cuda_bf16.h>
#include <cstdint>

#define B_   16
#define N_   1024
#define DIN_ 256
#define H_   4
#define F_   64
#define OUT_ 256

// -------- scratch (device globals) --------
__device__ float g_h[B_ * N_ * OUT_];        // h fp32 row-major
__device__ float g_esrc[B_ * H_ * N_];
__device__ float g_edst[B_ * H_ * N_];
// Interleaved B-fragment tiles, f-major: per (b, hd, chunk): gt[f*32 + col],
// col = kt*4+cc (j0 = chunk*128 + kt*16 + 2cc), uint4 =
// {hi(j0,j0+1), hi(j0+8,j0+9), lo(j0,j0+1), lo(j0+8,j0+9)}.
__device__ uint4 g_hTi[B_ * H_ * 8 * 2048];

// bf16 split helpers
__device__ __forceinline__ uint32_t hi_pack(float v0, float v1) {
    uint32_t r;
    asm("prmt.b32 %0, %1, %2, 0x7632;" : "=r"(r)
        : "r"(__float_as_uint(v0)), "r"(__float_as_uint(v1)));
    return r;
}
__device__ __forceinline__ uint32_t lo_pack(float v0, float v1) {
    float l0 = v0 - __uint_as_float(__float_as_uint(v0) & 0xFFFF0000u);
    float l1 = v1 - __uint_as_float(__float_as_uint(v1) & 0xFFFF0000u);
    uint32_t r;
    asm("cvt.rn.bf16x2.f32 %0, %1, %2;" : "=r"(r) : "f"(l1), "f"(l0));
    return r;
}

// warp-level bf16 MMA (HMMA path, sm_80+)
__device__ __forceinline__ void mma16816(float* c, uint32_t a0, uint32_t a1,
                                         uint32_t a2, uint32_t a3,
                                         uint32_t b0, uint32_t b1) {
    asm volatile(
        "mma.sync.aligned.m16n8k16.row.col.f32.bf16.bf16.f32 "
        "{%0,%1,%2,%3}, {%4,%5,%6,%7}, {%8,%9}, {%0,%1,%2,%3};"
        : "+f"(c[0]), "+f"(c[1]), "+f"(c[2]), "+f"(c[3])
        : "r"(a0), "r"(a1), "r"(a2), "r"(a3), "r"(b0), "r"(b1));
}

// ============================================================================
// Kernel 1: h = x @ W via split-bf16 HMMA (R9 version, measured 46.4 us).
// CTA = 128 rows x 128 cols (2 heads); grid (128, 2); 8 warps.
// Epilogue: h fp32 store + fused e_src/e_dst reductions.
// ============================================================================
__global__ __launch_bounds__(256, 2) void gemm_h_mma_kernel(
    const float* __restrict__ x, const float* __restrict__ W,
    const float* __restrict__ a_src, const float* __restrict__ a_dst)
{
    __shared__ uint32_t sxh[128 * 12];
    __shared__ uint32_t sxl[128 * 12];
    __shared__ uint4    swt[128 * 4];
    __shared__ float    sAs[256];
    __shared__ float    sAd[256];

    const int tid = threadIdx.x;
    const int wid = tid >> 5;
    const int l   = tid & 31;
    const int q   = l >> 2;
    const int c   = l & 3;
    const int R0  = blockIdx.x * 128;
    const int F0  = blockIdx.y * 128;

    if (tid < 256) { sAs[tid] = a_src[tid]; sAd[tid] = a_dst[tid]; }

    float acc[16][4];
#pragma unroll
    for (int nt = 0; nt < 16; nt++)
#pragma unroll
        for (int k = 0; k < 4; k++) acc[nt][k] = 0.f;

    const int xr = tid >> 1, xh = tid & 1;
    const int wf = tid >> 1, wh = tid & 1;

    for (int kt = 0; kt < 16; kt++) {
        __syncthreads();
        {
            const float* xp = x + (size_t)(R0 + xr) * DIN_ + kt * 16 + xh * 8;
            float4 a = *(const float4*)xp;
            float4 b = *(const float4*)(xp + 4);
            uint4 hi = make_uint4(hi_pack(a.x, a.y), hi_pack(a.z, a.w),
                                  hi_pack(b.x, b.y), hi_pack(b.z, b.w));
            uint4 lo = make_uint4(lo_pack(a.x, a.y), lo_pack(a.z, a.w),
                                  lo_pack(b.x, b.y), lo_pack(b.z, b.w));
            *(uint4*)&sxh[xr * 12 + xh * 4] = hi;
            *(uint4*)&sxl[xr * 12 + xh * 4] = lo;
        }
        {
#pragma unroll
            for (int t = 0; t < 2; t++) {
                int cc = wh * 2 + t;
                const float* wp = W + (size_t)(kt * 16 + 2 * cc) * OUT_ + F0 + wf;
                float w0 = wp[0];
                float w1 = wp[OUT_];
                float w2 = wp[8 * OUT_];
                float w3 = wp[9 * OUT_];
                swt[wf * 4 + cc] = make_uint4(hi_pack(w0, w1), hi_pack(w2, w3),
                                              lo_pack(w0, w1), lo_pack(w2, w3));
            }
        }
        __syncthreads();

        const int r0 = wid * 16 + q;
        const uint32_t ah0 = sxh[r0 * 12 + c];
        const uint32_t ah1 = sxh[(r0 + 8) * 12 + c];
        const uint32_t ah2 = sxh[r0 * 12 + c + 4];
        const uint32_t ah3 = sxh[(r0 + 8) * 12 + c + 4];
        const uint32_t al0 = sxl[r0 * 12 + c];
        const uint32_t al1 = sxl[(r0 + 8) * 12 + c];
        const uint32_t al2 = sxl[r0 * 12 + c + 4];
        const uint32_t al3 = sxl[(r0 + 8) * 12 + c + 4];

#pragma unroll
        for (int nt = 0; nt < 16; nt++) {
            uint4 v = swt[(nt * 8 + q) * 4 + c];
            mma16816(acc[nt], ah0, ah1, ah2, ah3, v.x, v.y);
            mma16816(acc[nt], ah0, ah1, ah2, ah3, v.z, v.w);
            mma16816(acc[nt], al0, al1, al2, al3, v.x, v.y);
        }
    }

    // ---- epilogue: store h fp32 + e_src/e_dst reductions ----
    const int gr0 = R0 + wid * 16 + q;
#pragma unroll
    for (int nt = 0; nt < 16; nt++) {
        const int gc = F0 + nt * 8 + 2 * c;
        *(float2*)(g_h + (size_t)gr0 * OUT_ + gc)       = make_float2(acc[nt][0], acc[nt][1]);
        *(float2*)(g_h + (size_t)(gr0 + 8) * OUT_ + gc) = make_float2(acc[nt][2], acc[nt][3]);
    }

    const int b = gr0 >> 10;
    const int n = gr0 & (N_ - 1);
#pragma unroll
    for (int hh = 0; hh < 2; hh++) {
        float ps0 = 0.f, ps1 = 0.f, pd0 = 0.f, pd1 = 0.f;
#pragma unroll
        for (int t = 0; t < 8; t++) {
            const int nt = hh * 8 + t;
            const int gc = F0 + nt * 8 + 2 * c;
            float2 as2 = *(float2*)&sAs[gc];
            float2 ad2 = *(float2*)&sAd[gc];
            ps0 += acc[nt][0] * as2.x + acc[nt][1] * as2.y;
            ps1 += acc[nt][2] * as2.x + acc[nt][3] * as2.y;
            pd0 += acc[nt][0] * ad2.x + acc[nt][1] * ad2.y;
            pd1 += acc[nt][2] * ad2.x + acc[nt][3] * ad2.y;
        }
#pragma unroll
        for (int off = 1; off <= 2; off <<= 1) {
            ps0 += __shfl_xor_sync(0xffffffffu, ps0, off);
            ps1 += __shfl_xor_sync(0xffffffffu, ps1, off);
            pd0 += __shfl_xor_sync(0xffffffffu, pd0, off);
            pd1 += __shfl_xor_sync(0xffffffffu, pd1, off);
        }
        if (c == 0) {
            const int hd = blockIdx.y * 2 + hh;
            g_esrc[(b * H_ + hd) * N_ + n]     = ps0;
            g_esrc[(b * H_ + hd) * N_ + n + 8] = ps1;
            g_edst[(b * H_ + hd) * N_ + n]     = pd0;
            g_edst[(b * H_ + hd) * N_ + n + 8] = pd1;
        }
    }
}

// ============================================================================
// Kernel 1b: transpose + split + pack h -> g_hTi (f-major pre-packed frags).
// CTA = one (b, 64-j block, head); grid 1024. Cols 0-15 of a chunk use the
// even 64-j half, cols 16-31 the odd half, so a 64-j CTA owns 16 cols.
// ============================================================================
__global__ __launch_bounds__(256) void transpose_pack_kernel()
{
    __shared__ float h_t[64 * 65];

    const int bid = blockIdx.x;
    const int hd  = bid & 3;
    const int jb  = (bid >> 2) & 15;   // 64-j block index; chunk = jb>>1, half = jb&1
    const int b   = bid >> 6;
    const int tid = threadIdx.x;

    for (int idx = tid; idx < 1024; idx += 256) {
        int j  = idx >> 4;
        int f4 = idx & 15;
        float4 v = *(const float4*)(g_h + (size_t)(b * N_ + jb * 64 + j) * OUT_ + hd * 64 + f4 * 4);
        h_t[(f4 * 4 + 0) * 65 + j] = v.x;
        h_t[(f4 * 4 + 1) * 65 + j] = v.y;
        h_t[(f4 * 4 + 2) * 65 + j] = v.z;
        h_t[(f4 * 4 + 3) * 65 + j] = v.w;
    }
    __syncthreads();

    const int chunk = jb >> 1;
    const int half  = jb & 1;
    uint4* gt = g_hTi + ((size_t)((b * H_ + hd) * 8 + chunk)) * 2048;

    const int f = tid >> 2;            // 0..63
#pragma unroll
    for (int v = 0; v < 4; v++) {
        const int colL = (tid & 3) * 4 + v;    // 0..15
        const int ktL  = colL >> 2;
        const int cc   = colL & 3;
        const int jL   = ktL * 16 + 2 * cc;    // 0..54
        float a0 = h_t[f * 65 + jL];
        float a1 = h_t[f * 65 + jL + 1];
        float a2 = h_t[f * 65 + jL + 8];
        float a3 = h_t[f * 65 + jL + 9];
        gt[f * 32 + half * 16 + colL] =
            make_uint4(hi_pack(a0, a1), hi_pack(a2, a3),
                       lo_pack(a0, a1), lo_pack(a2, a3));
    }
}

// ============================================================================
// Kernel 2: HMMA flash-GAT (R8 structure, measured 162.7 us), head-split,
// staging = pure uint4 copy from pre-packed g_hTi. Static smem 41 KB.
// CTA = (b, 128 i-rows, 2 heads); grid.z = 2; 8 warps.
// hbi row stride 36 uint4 (== 4 mod 8 -> conflict-free LDS.128 reads).
// ============================================================================
#define HBI_STR 36

__global__ __launch_bounds__(256, 2) void gat_attn_mma_kernel(
    const float* __restrict__ adj, const float* __restrict__ bias,
    float* __restrict__ out)
{
    __shared__ uint32_t abits[128][4];
    __shared__ float    es_sh[2][128];
    __shared__ float    ed_sh[2][128];
    __shared__ __align__(16) uint4 hbi[64 * HBI_STR];

    const int tid = threadIdx.x;
    const int wid = tid >> 5;
    const int l   = tid & 31;
    const int q   = l >> 2;
    const int c   = l & 3;
    const int b   = blockIdx.y;
    const int i0  = blockIdx.x * 128;
    const int hp  = blockIdx.z;          // head pair: heads hp*2, hp*2+1

    for (int idx = tid; idx < 2 * 128; idx += 256)
        ed_sh[idx >> 7][idx & 127] =
            g_edst[(b * H_ + hp * 2 + (idx >> 7)) * N_ + i0 + (idx & 127)];

    float acc[2][8][4];
    float den[2][2];
#pragma unroll
    for (int hh = 0; hh < 2; hh++) {
        den[hh][0] = 0.f; den[hh][1] = 0.f;
#pragma unroll
        for (int nt = 0; nt < 8; nt++)
#pragma unroll
            for (int k = 0; k < 4; k++) acc[hh][nt][k] = 0.f;
    }

    const float* adj_b = adj + (size_t)b * N_ * N_;

    for (int chunk = 0; chunk < 8; chunk++) {
        const int j0 = chunk * 128;
        __syncthreads();

        // adjacency bitmask: warp w handles its own 16 rows
#pragma unroll 4
        for (int k = 0; k < 16; k++) {
            int r = wid * 16 + k;
            const float* arow = adj_b + (size_t)(i0 + r) * N_ + j0;
#pragma unroll
            for (int jg = 0; jg < 4; jg++) {
                uint32_t m = __ballot_sync(0xffffffffu, arow[jg * 32 + l] > 0.5f);
                if (l == 0) abits[r][jg] = m;
            }
        }
        for (int idx = tid; idx < 2 * 128; idx += 256)
            es_sh[idx >> 7][idx & 127] =
                g_esrc[(b * H_ + hp * 2 + (idx >> 7)) * N_ + j0 + (idx & 127)];

#pragma unroll
        for (int hh = 0; hh < 2; hh++) {
            __syncthreads();
            // stage packed B fragments: pure copy, coalesced src, CF dst
            {
                const uint4* gt = g_hTi +
                    ((size_t)((b * H_ + hp * 2 + hh) * 8 + chunk)) * 2048;
#pragma unroll
                for (int v = 0; v < 8; v++) {
                    int idx = tid + v * 256;            // 0..2047
                    int f = idx >> 5, col = idx & 31;
                    hbi[f * HBI_STR + col] = gt[idx];
                }
            }
            __syncthreads();

            const int r0 = wid * 16 + q;
            const float ed0 = ed_sh[hh][r0];
            const float ed1 = ed_sh[hh][r0 + 8];
            float dsum0 = 0.f, dsum1 = 0.f;
#pragma unroll
            for (int kt = 0; kt < 8; kt++) {
                const int jA = kt * 16 + c * 2;
                float2 eA = *(const float2*)&es_sh[hh][jA];
                float2 eB = *(const float2*)&es_sh[hh][jA + 8];
                const uint32_t w0 = abits[r0][kt >> 1];
                const uint32_t w1 = abits[r0 + 8][kt >> 1];
                const int bb = ((kt & 1) << 4) + c * 2;

                float p00, p01, p08, p09, p10, p11, p18, p19;
                {
                    float s;
                    s = ed0 + eA.x; s = fmaxf(s, 0.2f * s); p00 = ((w0 >> bb) & 1u) ? __expf(s) : 0.f;
                    s = ed0 + eA.y; s = fmaxf(s, 0.2f * s); p01 = ((w0 >> (bb + 1)) & 1u) ? __expf(s) : 0.f;
                    s = ed0 + eB.x; s = fmaxf(s, 0.2f * s); p08 = ((w0 >> (bb + 8)) & 1u) ? __expf(s) : 0.f;
                    s = ed0 + eB.y; s = fmaxf(s, 0.2f * s); p09 = ((w0 >> (bb + 9)) & 1u) ? __expf(s) : 0.f;
                    s = ed1 + eA.x; s = fmaxf(s, 0.2f * s); p10 = ((w1 >> bb) & 1u) ? __expf(s) : 0.f;
                    s = ed1 + eA.y; s = fmaxf(s, 0.2f * s); p11 = ((w1 >> (bb + 1)) & 1u) ? __expf(s) : 0.f;
                    s = ed1 + eB.x; s = fmaxf(s, 0.2f * s); p18 = ((w1 >> (bb + 8)) & 1u) ? __expf(s) : 0.f;
                    s = ed1 + eB.y; s = fmaxf(s, 0.2f * s); p19 = ((w1 >> (bb + 9)) & 1u) ? __expf(s) : 0.f;
                }
                dsum0 += (p00 + p01) + (p08 + p09);
                dsum1 += (p10 + p11) + (p18 + p19);

                const uint32_t a0h = hi_pack(p00, p01), a1h = hi_pack(p10, p11);
                const uint32_t a2h = hi_pack(p08, p09), a3h = hi_pack(p18, p19);
                const uint32_t a0l = lo_pack(p00, p01), a1l = lo_pack(p10, p11);
                const uint32_t a2l = lo_pack(p08, p09), a3l = lo_pack(p18, p19);

#pragma unroll
                for (int nt = 0; nt < 8; nt++) {
                    uint4 v = hbi[(nt * 8 + q) * HBI_STR + kt * 4 + c];
                    mma16816(acc[hh][nt], a0h, a1h, a2h, a3h, v.x, v.y);
                    mma16816(acc[hh][nt], a0h, a1h, a2h, a3h, v.z, v.w);
                    mma16816(acc[hh][nt], a0l, a1l, a2l, a3l, v.x, v.y);
                }
            }
            den[hh][0] += dsum0;
            den[hh][1] += dsum1;
        }
    }

    // ---- epilogue: out = acc / den + bias ----
    const int gr0 = b * N_ + i0 + wid * 16 + q;
#pragma unroll
    for (int hh = 0; hh < 2; hh++) {
        float d0 = den[hh][0];
        d0 += __shfl_xor_sync(0xffffffffu, d0, 1);
        d0 += __shfl_xor_sync(0xffffffffu, d0, 2);
        float d1 = den[hh][1];
        d1 += __shfl_xor_sync(0xffffffffu, d1, 1);
        d1 += __shfl_xor_sync(0xffffffffu, d1, 2);
        const float rl0 = 1.0f / d0, rl1 = 1.0f / d1;
#pragma unroll
        for (int nt = 0; nt < 8; nt++) {
            const int col = (hp * 2 + hh) * 64 + nt * 8 + c * 2;
            float2 bv = __ldg((const float2*)(bias + col));
            float2 o0, o1;
            o0.x = acc[hh][nt][0] * rl0 + bv.x;
            o0.y = acc[hh][nt][1] * rl0 + bv.y;
            o1.x = acc[hh][nt][2] * rl1 + bv.x;
            o1.y = acc[hh][nt][3] * rl1 + bv.y;
            *(float2*)(out + (size_t)gr0 * OUT_ + col)       = o0;
            *(float2*)(out + (size_t)(gr0 + 8) * OUT_ + col) = o1;
        }
    }
}

// ============================================================================
extern "C" void kernel_launch(void* const* d_in, const int* in_sizes, int n_in,
                              void* d_out, int out_size)
{
    const float* x     = (const float*)d_in[0];
    const float* adj   = (const float*)d_in[1];
    const float* W     = (const float*)d_in[2];
    const float* a_src = (const float*)d_in[3];
    const float* a_dst = (const float*)d_in[4];
    const float* bias  = (const float*)d_in[5];
    float* out = (float*)d_out;

    gemm_h_mma_kernel<<<dim3((B_ * N_) / 128, 2), 256>>>(x, W, a_src, a_dst);
    transpose_pack_kernel<<<B_ * 16 * H_, 256>>>();
    gat_attn_mma_kernel<<<dim3(N_ / 128, B_, 2), 256>>>(adj, bias, out);
}